// round 15
// baseline (speedup 1.0000x reference)
#include <cuda_runtime.h>
#include <cuda_fp16.h>
#include <cstdint>

// Problem constants (B=4, T=4096, C=1024, H=16, D=64, BLOCK=128)
#define B_    4
#define T_    4096
#define C_    1024
#define H_    16
#define Dh_   64
#define BS_   128
#define M_TOK 16384
#define N_QKV 3072
#define KDIM  1024

// Scratch (allocation-free rule: __device__ globals)
__device__ __half g_qkvh  [(size_t)M_TOK * N_QKV];  // 96 MiB
__device__ __half g_attnh [(size_t)M_TOK * C_];     // 32 MiB
__device__ __half g_xh    [(size_t)M_TOK * C_];     // 32 MiB
__device__ __half g_WqkvT [(size_t)N_QKV * KDIM];   // 6 MiB  [N][K]
__device__ __half g_WprojT[(size_t)C_ * KDIM];      // 2 MiB  [N][K]

// ---------------------------------------------------------------------------
// helpers
// ---------------------------------------------------------------------------
__device__ __forceinline__ uint32_t smem_u32(const void* p) {
    uint32_t a;
    asm("{ .reg .u64 t; cvta.to.shared.u64 t, %1; cvt.u32.u64 %0, t; }" : "=r"(a) : "l"(p));
    return a;
}
// D += A*B, m16n8k16 f16 inputs, f32 accum
__device__ __forceinline__ void mma_f16(float* d, const uint32_t* a, const uint32_t* b) {
    asm volatile(
        "mma.sync.aligned.m16n8k16.row.col.f32.f16.f16.f32 "
        "{%0,%1,%2,%3}, {%4,%5,%6,%7}, {%8,%9}, {%0,%1,%2,%3};"
        : "+f"(d[0]), "+f"(d[1]), "+f"(d[2]), "+f"(d[3])
        : "r"(a[0]), "r"(a[1]), "r"(a[2]), "r"(a[3]), "r"(b[0]), "r"(b[1]));
}
#define LDSM4(r0, r1, r2, r3, addr) \
    asm volatile("ldmatrix.sync.aligned.m8n8.x4.shared.b16 {%0,%1,%2,%3}, [%4];" \
                 : "=r"(r0), "=r"(r1), "=r"(r2), "=r"(r3) : "r"(addr))
#define LDSM4T(r0, r1, r2, r3, addr) \
    asm volatile("ldmatrix.sync.aligned.m8n8.x4.trans.shared.b16 {%0,%1,%2,%3}, [%4];" \
                 : "=r"(r0), "=r"(r1), "=r"(r2), "=r"(r3) : "r"(addr))
#define CP16(dst, src) \
    asm volatile("cp.async.cg.shared.global [%0], [%1], 16;" :: "r"(dst), "l"(src))
#define CP_COMMIT() asm volatile("cp.async.commit_group;")
#define CP_WAIT0()  asm volatile("cp.async.wait_group 0;")

// ---------------------------------------------------------------------------
// conversion kernels
// ---------------------------------------------------------------------------
__global__ void cvt_f2h(const float4* __restrict__ in, uint2* __restrict__ out, int n4) {
    int i = blockIdx.x * blockDim.x + threadIdx.x;
    if (i < n4) {
        float4 v = in[i];
        __half2 h0 = __floats2half2_rn(v.x, v.y);
        __half2 h1 = __floats2half2_rn(v.z, v.w);
        out[i] = make_uint2(*(uint32_t*)&h0, *(uint32_t*)&h1);
    }
}
// in fp32 [R][Cc] -> out half [Cc][R]
__global__ void transpose_cvt(const float* __restrict__ in, __half* __restrict__ out,
                              int R, int Cc)
{
    __shared__ float t[32][33];
    int x = blockIdx.x * 32 + threadIdx.x;
    int y = blockIdx.y * 32 + threadIdx.y;
#pragma unroll
    for (int j = 0; j < 32; j += 8)
        t[threadIdx.y + j][threadIdx.x] = in[(size_t)(y + j) * Cc + x];
    __syncthreads();
    int x2 = blockIdx.y * 32 + threadIdx.x;
    int y2 = blockIdx.x * 32 + threadIdx.y;
#pragma unroll
    for (int j = 0; j < 32; j += 8)
        out[(size_t)(y2 + j) * R + x2] = __float2half(t[threadIdx.x][threadIdx.y + j]);
}

// ---------------------------------------------------------------------------
// fp16 mma GEMM (verbatim R14 — best measured): 128x128 CTA tiles, BK=64,
// 3-stage cp.async, 4 warps (2x2), 64x64 warp tile, ldmatrix, XOR swizzle,
// fragment double buffering with cross-iteration prefetch.
// ---------------------------------------------------------------------------
#define ROWB     128
#define ASTG_B   (128 * ROWB)
#define STG_B    (2 * ASTG_B)
#define GSMEM_B  (3 * STG_B)

__device__ __forceinline__ uint32_t swz(uint32_t row, uint32_t g) {
    return row * ROWB + (((g ^ (row & 7)) & 7) << 4);
}

template <bool BIAS, bool HALF_OUT>
__global__ __launch_bounds__(128, 2)
void gemm_h(const __half* __restrict__ A, const __half* __restrict__ Bt,
            const float* __restrict__ bias, void* __restrict__ Cout, int N)
{
    extern __shared__ __half smh[];
    const uint32_t sb = smem_u32(smh);
    const int tid = threadIdx.x, lane = tid & 31, wid = tid >> 5;
    const int wm = wid >> 1, wn = wid & 1, gr = lane >> 2, ctg = lane & 3;
    const int bm = blockIdx.y * 128, bn = blockIdx.x * 128;

    const __half* pA = A + (size_t)(bm + (tid >> 3)) * KDIM + (tid & 7) * 8;
    const __half* pB = Bt + (size_t)(bn + (tid >> 3)) * KDIM + (tid & 7) * 8;
    const uint32_t dA0 = sb + swz((uint32_t)(tid >> 3), (uint32_t)(tid & 7));
    const uint32_t dB0 = dA0 + ASTG_B;

    auto load_tile = [&](int s, int k0) {
        const uint32_t so = (uint32_t)(s * STG_B);
#pragma unroll
        for (int i = 0; i < 8; i++)
            CP16(dA0 + so + (uint32_t)(i * 16 * ROWB), pA + k0 + (size_t)i * 16 * KDIM);
#pragma unroll
        for (int i = 0; i < 8; i++)
            CP16(dB0 + so + (uint32_t)(i * 16 * ROWB), pB + k0 + (size_t)i * 16 * KDIM);
    };

    const uint32_t rA  = (uint32_t)(wm * 64 + (lane & 15));
    const uint32_t gA0 = (uint32_t)(lane >> 4);
    const uint32_t rB  = (uint32_t)(wn * 64 + ((lane & 16) >> 1) + (lane & 7));
    const uint32_t gB0 = (uint32_t)((lane & 8) >> 3);

    float acc[4][8][4] = {};
    uint32_t a[2][4][4], bf[2][8][2];

    auto ldfrags = [&](int buf, uint32_t sA, uint32_t sB, int kk) {
        const uint32_t gA = 2 * kk + gA0;
        const uint32_t gB = 2 * kk + gB0;
#pragma unroll
        for (int mi = 0; mi < 4; ++mi)
            LDSM4(a[buf][mi][0], a[buf][mi][1], a[buf][mi][2], a[buf][mi][3],
                  sA + swz(rA + mi * 16, gA));
#pragma unroll
        for (int pn = 0; pn < 4; ++pn)
            LDSM4(bf[buf][2 * pn][0], bf[buf][2 * pn][1],
                  bf[buf][2 * pn + 1][0], bf[buf][2 * pn + 1][1],
                  sB + swz(rB + pn * 16, gB));
    };

    // prologue: tiles 0 and 1 both complete & visible, frags for (tile0,kk0)
    load_tile(0, 0);  CP_COMMIT();
    load_tile(1, 64); CP_COMMIT();
    CP_WAIT0();
    __syncthreads();
    ldfrags(0, sb, sb + ASTG_B, 0);

    for (int it = 0; it < 16; ++it) {
        const uint32_t sA = sb + (uint32_t)((it % 3) * STG_B);
        const uint32_t sB = sA + ASTG_B;
        const uint32_t nA = sb + (uint32_t)(((it + 1) % 3) * STG_B);
        const uint32_t nB = nA + ASTG_B;

        if (it + 2 < 16) { load_tile((it + 2) % 3, (it + 2) * 64); CP_COMMIT(); }

#pragma unroll
        for (int kk = 0; kk < 4; ++kk) {
            const int cur = kk & 1;
            if (kk < 3)       ldfrags(cur ^ 1, sA, sB, kk + 1);
            else if (it < 15) ldfrags(cur ^ 1, nA, nB, 0);   // cross-iter prefetch
#pragma unroll
            for (int mi = 0; mi < 4; ++mi)
#pragma unroll
                for (int ni = 0; ni < 8; ++ni)
                    mma_f16(acc[mi][ni], a[cur][mi], bf[cur][ni]);
        }

        if (it + 2 < 16) {
            CP_WAIT0();
            __syncthreads();
        }
    }

#pragma unroll
    for (int mi = 0; mi < 4; mi++) {
        int r0 = bm + wm * 64 + mi * 16 + gr;
#pragma unroll
        for (int ni = 0; ni < 8; ni++) {
            int c0 = bn + wn * 64 + ni * 8 + 2 * ctg;
            if (HALF_OUT) {
                __half* C = (__half*)Cout;
                __half2 v0 = __floats2half2_rn(acc[mi][ni][0], acc[mi][ni][1]);
                __half2 v1 = __floats2half2_rn(acc[mi][ni][2], acc[mi][ni][3]);
                *(__half2*)&C[(size_t)r0 * N + c0]       = v0;
                *(__half2*)&C[(size_t)(r0 + 8) * N + c0] = v1;
            } else {
                float* C = (float*)Cout;
                float bx = 0.f, by = 0.f;
                if (BIAS) { bx = bias[c0]; by = bias[c0 + 1]; }
                float2 v0 = make_float2(acc[mi][ni][0] + bx, acc[mi][ni][1] + by);
                float2 v1 = make_float2(acc[mi][ni][2] + bx, acc[mi][ni][3] + by);
                *(float2*)&C[(size_t)r0 * N + c0]       = v0;
                *(float2*)&C[(size_t)(r0 + 8) * N + c0] = v1;
            }
        }
    }
}

// ---------------------------------------------------------------------------
// Block-local causal attention — R13 + intra-chunk pipelining:
//   * all 4 K-LDSMs batched up front (latencies overlap, MLP=4)
//   * V-LDSM4Ts hoisted before the exp block (MUFU burst hides V latency)
// grid = (H, T/128, B), 256 threads; Q frags hoisted out of the kt loop.
// ---------------------------------------------------------------------------
#define QPH 72
#define AOFF_Q 0
#define AOFF_K (128 * QPH)
#define AOFF_V (2 * 128 * QPH)
#define ATT2_B (3 * 128 * QPH * 2)           // 55296 bytes

__global__ __launch_bounds__(256)
void attn_h(const __half* __restrict__ qkv, __half* __restrict__ outp)
{
    extern __shared__ __half smh[];
    const uint32_t sbA = smem_u32(smh);
    const int h = blockIdx.x, blk = blockIdx.y, b = blockIdx.z;
    const int token0 = b * T_ + blk * BS_;
    const __half* qp = qkv + (size_t)token0 * N_QKV + h * Dh_;
    const __half* kp = qp + C_;
    const __half* vp = qp + 2 * C_;

    const int tid = threadIdx.x, lane = tid & 31, wid = tid >> 5;
    const int gr = lane >> 2, ctg = lane & 3;

    __half* Qs = smh + AOFF_Q;
    __half* Ks = smh + AOFF_K;
    __half* Vs = smh + AOFF_V;
    const uint32_t uQ = sbA + AOFF_Q * 2;
    const uint32_t uK = sbA + AOFF_K * 2;
    const uint32_t uV = sbA + AOFF_V * 2;

    for (int i = tid; i < 1024; i += 256) {
        int r = i >> 3, c8 = (i & 7) << 3;
        *(uint4*)&Qs[r * QPH + c8] = *(const uint4*)(qp + (size_t)r * N_QKV + c8);
        *(uint4*)&Ks[r * QPH + c8] = *(const uint4*)(kp + (size_t)r * N_QKV + c8);
        *(uint4*)&Vs[r * QPH + c8] = *(const uint4*)(vp + (size_t)r * N_QKV + c8);
    }
    __syncthreads();

    const uint32_t aOffQ = (uint32_t)((wid * 16 + (lane & 15)) * QPH + ((lane >> 4) << 3)) * 2;
    const uint32_t bOffK = (uint32_t)((((lane & 16) >> 1) + (lane & 7)) * QPH
                                      + ((lane & 8) ? 8 : 0)) * 2;
    const uint32_t bOffV = (uint32_t)(((lane & 7) + ((lane & 8) ? 8 : 0)) * QPH
                                      + ((lane & 16) ? 8 : 0)) * 2;

    // hoist Q fragments (invariant across kt)
    uint32_t qf[4][4];
#pragma unroll
    for (int kk = 0; kk < 4; ++kk)
        LDSM4(qf[kk][0], qf[kk][1], qf[kk][2], qf[kk][3], uQ + aOffQ + kk * 32);

    float oa[8][4] = {};
    float rs0 = 0.f, rs1 = 0.f;

    for (int kt = 0; kt <= wid; ++kt) {
        const uint32_t kBase = uK + bOffK + (uint32_t)(kt * 16 * QPH) * 2;
        const uint32_t vBase = uV + bOffV + (uint32_t)(kt * 16 * QPH) * 2;

        // batch all K-LDSMs (latencies overlap)
        uint32_t kf[4][4];
#pragma unroll
        for (int kk = 0; kk < 4; ++kk)
            LDSM4(kf[kk][0], kf[kk][1], kf[kk][2], kf[kk][3], kBase + kk * 32);

        // S MMAs
        float sa[2][4] = {};
#pragma unroll
        for (int kk = 0; kk < 4; ++kk) {
            uint32_t bf0[2] = {kf[kk][0], kf[kk][1]}, bf1[2] = {kf[kk][2], kf[kk][3]};
            mma_f16(sa[0], qf[kk], bf0);
            mma_f16(sa[1], qf[kk], bf1);
        }

        // V prefetch (independent of sa; exp block below hides its latency)
        uint32_t vf[4][4];
#pragma unroll
        for (int j2 = 0; j2 < 4; ++j2)
            LDSM4T(vf[j2][0], vf[j2][1], vf[j2][2], vf[j2][3],
                   vBase + (uint32_t)(j2 * 16) * 2);

        // mask + exp + rowsum
        const bool diag = (kt == wid);
#pragma unroll
        for (int j = 0; j < 2; ++j)
#pragma unroll
            for (int e = 0; e < 4; ++e) {
                int col  = j * 8 + 2 * ctg + (e & 1);
                int rowi = gr + ((e >= 2) ? 8 : 0);
                float v = (!diag || (col <= rowi)) ?
                          __expf(sa[j][e] * 0.125f) : 0.f;
                sa[j][e] = v;
                if (e < 2) rs0 += v; else rs1 += v;
            }

        // P c-frag -> A-frag
        uint32_t pa[4];
        {
            __half2 t0 = __floats2half2_rn(sa[0][0], sa[0][1]);
            __half2 t1 = __floats2half2_rn(sa[0][2], sa[0][3]);
            __half2 t2 = __floats2half2_rn(sa[1][0], sa[1][1]);
            __half2 t3 = __floats2half2_rn(sa[1][2], sa[1][3]);
            pa[0] = *(uint32_t*)&t0;  pa[1] = *(uint32_t*)&t1;
            pa[2] = *(uint32_t*)&t2;  pa[3] = *(uint32_t*)&t3;
        }

        // P·V
#pragma unroll
        for (int j2 = 0; j2 < 4; ++j2) {
            uint32_t bf0[2] = {vf[j2][0], vf[j2][1]}, bf1[2] = {vf[j2][2], vf[j2][3]};
            mma_f16(oa[2 * j2],     pa, bf0);
            mma_f16(oa[2 * j2 + 1], pa, bf1);
        }
    }

    {
        float s0 = rs0, s1 = rs1;
        s0 += __shfl_xor_sync(0xffffffffu, s0, 1);
        s0 += __shfl_xor_sync(0xffffffffu, s0, 2);
        s1 += __shfl_xor_sync(0xffffffffu, s1, 1);
        s1 += __shfl_xor_sync(0xffffffffu, s1, 2);
        float inv0 = __fdividef(1.f, s0 + 1e-6f);
        float inv1 = __fdividef(1.f, s1 + 1e-6f);

        __half* op = outp + (size_t)token0 * C_ + h * Dh_;
        int r0 = wid * 16 + gr;
#pragma unroll
        for (int jt = 0; jt < 8; ++jt) {
            int c0 = jt * 8 + 2 * ctg;
            __half2 v0 = __floats2half2_rn(oa[jt][0] * inv0, oa[jt][1] * inv0);
            __half2 v1 = __floats2half2_rn(oa[jt][2] * inv1, oa[jt][3] * inv1);
            *(__half2*)&op[(size_t)r0 * C_ + c0]       = v0;
            *(__half2*)&op[(size_t)(r0 + 8) * C_ + c0] = v1;
        }
    }
}

// ---------------------------------------------------------------------------
extern "C" void kernel_launch(void* const* d_in, const int* in_sizes, int n_in,
                              void* d_out, int out_size)
{
    const float* x      = (const float*)d_in[0];
    const float* W_qkv  = (const float*)d_in[1];
    const float* W_proj = (const float*)d_in[2];
    const float* b_proj = (const float*)d_in[3];
    float* out = (float*)d_out;

    __half *qkvh, *attnh, *xh, *WqkvT, *WprojT;
    cudaGetSymbolAddress((void**)&qkvh,   g_qkvh);
    cudaGetSymbolAddress((void**)&attnh,  g_attnh);
    cudaGetSymbolAddress((void**)&xh,     g_xh);
    cudaGetSymbolAddress((void**)&WqkvT,  g_WqkvT);
    cudaGetSymbolAddress((void**)&WprojT, g_WprojT);

    static bool attr_set = false;
    if (!attr_set) {
        cudaFuncSetAttribute((const void*)gemm_h<false, true>,
                             cudaFuncAttributeMaxDynamicSharedMemorySize, GSMEM_B);
        cudaFuncSetAttribute((const void*)gemm_h<true, false>,
                             cudaFuncAttributeMaxDynamicSharedMemorySize, GSMEM_B);
        cudaFuncSetAttribute((const void*)attn_h,
                             cudaFuncAttributeMaxDynamicSharedMemorySize, ATT2_B);
        attr_set = true;
    }

    // 0) fp16 conversions
    cvt_f2h<<<(M_TOK * C_ / 4 + 255) / 256, 256>>>((const float4*)x, (uint2*)xh,
                                                   M_TOK * C_ / 4);
    transpose_cvt<<<dim3(N_QKV / 32, KDIM / 32), dim3(32, 8)>>>(W_qkv, WqkvT, KDIM, N_QKV);
    transpose_cvt<<<dim3(C_ / 32, KDIM / 32), dim3(32, 8)>>>(W_proj, WprojT, KDIM, C_);

    // 1) qkv = x @ W_qkv  (fp16 mma, fp16 out)
    gemm_h<false, true><<<dim3(N_QKV / 128, M_TOK / 128), 128, GSMEM_B>>>(
        xh, WqkvT, nullptr, qkvh, N_QKV);

    // 2) block-local causal attention (fp16 mma, pipelined chunks)
    attn_h<<<dim3(H_, T_ / BS_, B_), 256, ATT2_B>>>(qkvh, attnh);

    // 3) out = attn @ W_proj + b_proj (fp16 mma, fp32 out)
    gemm_h<true, false><<<dim3(C_ / 128, M_TOK / 128), 128, GSMEM_B>>>(
        attnh, WprojT, b_proj, out, C_);
}

// round 16
// speedup vs baseline: 1.0350x; 1.0350x over previous
#include <cuda_runtime.h>
#include <cuda_fp16.h>
#include <cstdint>

// Problem constants (B=4, T=4096, C=1024, H=16, D=64, BLOCK=128)
#define B_    4
#define T_    4096
#define C_    1024
#define H_    16
#define Dh_   64
#define BS_   128
#define M_TOK 16384
#define N_QKV 3072
#define KDIM  1024

// Scratch (allocation-free rule: __device__ globals)
__device__ __half g_qkvh  [(size_t)M_TOK * N_QKV];  // 96 MiB
__device__ __half g_attnh [(size_t)M_TOK * C_];     // 32 MiB
__device__ __half g_xh    [(size_t)M_TOK * C_];     // 32 MiB
__device__ __half g_WqkvT [(size_t)N_QKV * KDIM];   // 6 MiB  [N][K]
__device__ __half g_WprojT[(size_t)C_ * KDIM];      // 2 MiB  [N][K]

// ---------------------------------------------------------------------------
// helpers
// ---------------------------------------------------------------------------
__device__ __forceinline__ uint32_t smem_u32(const void* p) {
    uint32_t a;
    asm("{ .reg .u64 t; cvta.to.shared.u64 t, %1; cvt.u32.u64 %0, t; }" : "=r"(a) : "l"(p));
    return a;
}
// D += A*B, m16n8k16 f16 inputs, f32 accum
__device__ __forceinline__ void mma_f16(float* d, const uint32_t* a, const uint32_t* b) {
    asm volatile(
        "mma.sync.aligned.m16n8k16.row.col.f32.f16.f16.f32 "
        "{%0,%1,%2,%3}, {%4,%5,%6,%7}, {%8,%9}, {%0,%1,%2,%3};"
        : "+f"(d[0]), "+f"(d[1]), "+f"(d[2]), "+f"(d[3])
        : "r"(a[0]), "r"(a[1]), "r"(a[2]), "r"(a[3]), "r"(b[0]), "r"(b[1]));
}
#define LDSM4(r0, r1, r2, r3, addr) \
    asm volatile("ldmatrix.sync.aligned.m8n8.x4.shared.b16 {%0,%1,%2,%3}, [%4];" \
                 : "=r"(r0), "=r"(r1), "=r"(r2), "=r"(r3) : "r"(addr))
#define LDSM4T(r0, r1, r2, r3, addr) \
    asm volatile("ldmatrix.sync.aligned.m8n8.x4.trans.shared.b16 {%0,%1,%2,%3}, [%4];" \
                 : "=r"(r0), "=r"(r1), "=r"(r2), "=r"(r3) : "r"(addr))
#define CP16(dst, src) \
    asm volatile("cp.async.cg.shared.global [%0], [%1], 16;" :: "r"(dst), "l"(src))
#define CP_COMMIT() asm volatile("cp.async.commit_group;")
#define CP_WAIT0()  asm volatile("cp.async.wait_group 0;")
#define CP_WAIT1()  asm volatile("cp.async.wait_group 1;")

// ---------------------------------------------------------------------------
// conversion kernels
// ---------------------------------------------------------------------------
__global__ void cvt_f2h(const float4* __restrict__ in, uint2* __restrict__ out, int n4) {
    int i = blockIdx.x * blockDim.x + threadIdx.x;
    if (i < n4) {
        float4 v = in[i];
        __half2 h0 = __floats2half2_rn(v.x, v.y);
        __half2 h1 = __floats2half2_rn(v.z, v.w);
        out[i] = make_uint2(*(uint32_t*)&h0, *(uint32_t*)&h1);
    }
}
// in fp32 [R][Cc] -> out half [Cc][R]
__global__ void transpose_cvt(const float* __restrict__ in, __half* __restrict__ out,
                              int R, int Cc)
{
    __shared__ float t[32][33];
    int x = blockIdx.x * 32 + threadIdx.x;
    int y = blockIdx.y * 32 + threadIdx.y;
#pragma unroll
    for (int j = 0; j < 32; j += 8)
        t[threadIdx.y + j][threadIdx.x] = in[(size_t)(y + j) * Cc + x];
    __syncthreads();
    int x2 = blockIdx.y * 32 + threadIdx.x;
    int y2 = blockIdx.x * 32 + threadIdx.y;
#pragma unroll
    for (int j = 0; j < 32; j += 8)
        out[(size_t)(y2 + j) * R + x2] = __float2half(t[threadIdx.x][threadIdx.y + j]);
}

// ---------------------------------------------------------------------------
// fp16 mma GEMM (verbatim R14 — best measured): 128x128 CTA tiles, BK=64,
// 3-stage cp.async, 4 warps (2x2), 64x64 warp tile, ldmatrix, XOR swizzle,
// fragment double buffering with cross-iteration prefetch.
// ---------------------------------------------------------------------------
#define ROWB     128
#define ASTG_B   (128 * ROWB)
#define STG_B    (2 * ASTG_B)
#define GSMEM_B  (3 * STG_B)

__device__ __forceinline__ uint32_t swz(uint32_t row, uint32_t g) {
    return row * ROWB + (((g ^ (row & 7)) & 7) << 4);
}

template <bool BIAS, bool HALF_OUT>
__global__ __launch_bounds__(128, 2)
void gemm_h(const __half* __restrict__ A, const __half* __restrict__ Bt,
            const float* __restrict__ bias, void* __restrict__ Cout, int N)
{
    extern __shared__ __half smh[];
    const uint32_t sb = smem_u32(smh);
    const int tid = threadIdx.x, lane = tid & 31, wid = tid >> 5;
    const int wm = wid >> 1, wn = wid & 1, gr = lane >> 2, ctg = lane & 3;
    const int bm = blockIdx.y * 128, bn = blockIdx.x * 128;

    const __half* pA = A + (size_t)(bm + (tid >> 3)) * KDIM + (tid & 7) * 8;
    const __half* pB = Bt + (size_t)(bn + (tid >> 3)) * KDIM + (tid & 7) * 8;
    const uint32_t dA0 = sb + swz((uint32_t)(tid >> 3), (uint32_t)(tid & 7));
    const uint32_t dB0 = dA0 + ASTG_B;

    auto load_tile = [&](int s, int k0) {
        const uint32_t so = (uint32_t)(s * STG_B);
#pragma unroll
        for (int i = 0; i < 8; i++)
            CP16(dA0 + so + (uint32_t)(i * 16 * ROWB), pA + k0 + (size_t)i * 16 * KDIM);
#pragma unroll
        for (int i = 0; i < 8; i++)
            CP16(dB0 + so + (uint32_t)(i * 16 * ROWB), pB + k0 + (size_t)i * 16 * KDIM);
    };

    const uint32_t rA  = (uint32_t)(wm * 64 + (lane & 15));
    const uint32_t gA0 = (uint32_t)(lane >> 4);
    const uint32_t rB  = (uint32_t)(wn * 64 + ((lane & 16) >> 1) + (lane & 7));
    const uint32_t gB0 = (uint32_t)((lane & 8) >> 3);

    float acc[4][8][4] = {};
    uint32_t a[2][4][4], bf[2][8][2];

    auto ldfrags = [&](int buf, uint32_t sA, uint32_t sB, int kk) {
        const uint32_t gA = 2 * kk + gA0;
        const uint32_t gB = 2 * kk + gB0;
#pragma unroll
        for (int mi = 0; mi < 4; ++mi)
            LDSM4(a[buf][mi][0], a[buf][mi][1], a[buf][mi][2], a[buf][mi][3],
                  sA + swz(rA + mi * 16, gA));
#pragma unroll
        for (int pn = 0; pn < 4; ++pn)
            LDSM4(bf[buf][2 * pn][0], bf[buf][2 * pn][1],
                  bf[buf][2 * pn + 1][0], bf[buf][2 * pn + 1][1],
                  sB + swz(rB + pn * 16, gB));
    };

    // prologue: tiles 0 and 1 both complete & visible, frags for (tile0,kk0)
    load_tile(0, 0);  CP_COMMIT();
    load_tile(1, 64); CP_COMMIT();
    CP_WAIT0();
    __syncthreads();
    ldfrags(0, sb, sb + ASTG_B, 0);

    for (int it = 0; it < 16; ++it) {
        const uint32_t sA = sb + (uint32_t)((it % 3) * STG_B);
        const uint32_t sB = sA + ASTG_B;
        const uint32_t nA = sb + (uint32_t)(((it + 1) % 3) * STG_B);
        const uint32_t nB = nA + ASTG_B;

        if (it + 2 < 16) { load_tile((it + 2) % 3, (it + 2) * 64); CP_COMMIT(); }

#pragma unroll
        for (int kk = 0; kk < 4; ++kk) {
            const int cur = kk & 1;
            if (kk < 3)       ldfrags(cur ^ 1, sA, sB, kk + 1);
            else if (it < 15) ldfrags(cur ^ 1, nA, nB, 0);   // cross-iter prefetch
#pragma unroll
            for (int mi = 0; mi < 4; ++mi)
#pragma unroll
                for (int ni = 0; ni < 8; ++ni)
                    mma_f16(acc[mi][ni], a[cur][mi], bf[cur][ni]);
        }

        if (it + 2 < 16) {
            CP_WAIT0();
            __syncthreads();
        }
    }

#pragma unroll
    for (int mi = 0; mi < 4; mi++) {
        int r0 = bm + wm * 64 + mi * 16 + gr;
#pragma unroll
        for (int ni = 0; ni < 8; ni++) {
            int c0 = bn + wn * 64 + ni * 8 + 2 * ctg;
            if (HALF_OUT) {
                __half* C = (__half*)Cout;
                __half2 v0 = __floats2half2_rn(acc[mi][ni][0], acc[mi][ni][1]);
                __half2 v1 = __floats2half2_rn(acc[mi][ni][2], acc[mi][ni][3]);
                *(__half2*)&C[(size_t)r0 * N + c0]       = v0;
                *(__half2*)&C[(size_t)(r0 + 8) * N + c0] = v1;
            } else {
                float* C = (float*)Cout;
                float bx = 0.f, by = 0.f;
                if (BIAS) { bx = bias[c0]; by = bias[c0 + 1]; }
                float2 v0 = make_float2(acc[mi][ni][0] + bx, acc[mi][ni][1] + by);
                float2 v1 = make_float2(acc[mi][ni][2] + bx, acc[mi][ni][3] + by);
                *(float2*)&C[(size_t)r0 * N + c0]       = v0;
                *(float2*)&C[(size_t)(r0 + 8) * N + c0] = v1;
            }
        }
    }
}

// ---------------------------------------------------------------------------
// Block-local causal attention — async split loads + peeled first chunk.
//   * Q/K/V filled via cp.async (no LDG->reg->STS round trip)
//   * two commit groups: (Q,K) then V
//   * wait_group 1 -> compute S(kt=0) while V still in flight
//   * wait_group 0 -> finish chunk 0, run remaining chunks (R15 body)
// grid = (H, T/128, B), 256 threads; Q frags hoisted.
// ---------------------------------------------------------------------------
#define QPH 72
#define AOFF_Q 0
#define AOFF_K (128 * QPH)
#define AOFF_V (2 * 128 * QPH)
#define ATT2_B (3 * 128 * QPH * 2)           // 55296 bytes

__global__ __launch_bounds__(256)
void attn_h(const __half* __restrict__ qkv, __half* __restrict__ outp)
{
    extern __shared__ __half smh[];
    const uint32_t sbA = smem_u32(smh);
    const int h = blockIdx.x, blk = blockIdx.y, b = blockIdx.z;
    const int token0 = b * T_ + blk * BS_;
    const __half* qp = qkv + (size_t)token0 * N_QKV + h * Dh_;
    const __half* kp = qp + C_;
    const __half* vp = qp + 2 * C_;

    const int tid = threadIdx.x, lane = tid & 31, wid = tid >> 5;
    const int gr = lane >> 2, ctg = lane & 3;

    const uint32_t uQ = sbA + AOFF_Q * 2;
    const uint32_t uK = sbA + AOFF_K * 2;
    const uint32_t uV = sbA + AOFF_V * 2;

    // async fill: group 0 = Q+K, group 1 = V (each thread: 4 rows x 16B)
    {
        const int r = tid >> 3, c8 = (tid & 7) << 3;
        const uint32_t so = (uint32_t)(r * QPH + c8) * 2;
        const size_t go = (size_t)r * N_QKV + c8;
#pragma unroll
        for (int i = 0; i < 4; ++i) {
            CP16(uQ + so + (uint32_t)(i * 32 * QPH) * 2, qp + go + (size_t)i * 32 * N_QKV);
            CP16(uK + so + (uint32_t)(i * 32 * QPH) * 2, kp + go + (size_t)i * 32 * N_QKV);
        }
        CP_COMMIT();
#pragma unroll
        for (int i = 0; i < 4; ++i)
            CP16(uV + so + (uint32_t)(i * 32 * QPH) * 2, vp + go + (size_t)i * 32 * N_QKV);
        CP_COMMIT();
    }

    const uint32_t aOffQ = (uint32_t)((wid * 16 + (lane & 15)) * QPH + ((lane >> 4) << 3)) * 2;
    const uint32_t bOffK = (uint32_t)((((lane & 16) >> 1) + (lane & 7)) * QPH
                                      + ((lane & 8) ? 8 : 0)) * 2;
    const uint32_t bOffV = (uint32_t)(((lane & 7) + ((lane & 8) ? 8 : 0)) * QPH
                                      + ((lane & 16) ? 8 : 0)) * 2;

    CP_WAIT1();            // Q, K visible (after barrier)
    __syncthreads();

    // hoist Q fragments (invariant across kt)
    uint32_t qf[4][4];
#pragma unroll
    for (int kk = 0; kk < 4; ++kk)
        LDSM4(qf[kk][0], qf[kk][1], qf[kk][2], qf[kk][3], uQ + aOffQ + kk * 32);

    float oa[8][4] = {};
    float rs0 = 0.f, rs1 = 0.f;

    // ---- peeled chunk kt = 0: S while V is still loading ----
    float sa[2][4] = {};
    {
        uint32_t kf[4][4];
#pragma unroll
        for (int kk = 0; kk < 4; ++kk)
            LDSM4(kf[kk][0], kf[kk][1], kf[kk][2], kf[kk][3], uK + bOffK + kk * 32);
#pragma unroll
        for (int kk = 0; kk < 4; ++kk) {
            uint32_t bf0[2] = {kf[kk][0], kf[kk][1]}, bf1[2] = {kf[kk][2], kf[kk][3]};
            mma_f16(sa[0], qf[kk], bf0);
            mma_f16(sa[1], qf[kk], bf1);
        }
    }

    CP_WAIT0();            // V visible (after barrier)
    __syncthreads();

    for (int kt = 0; kt <= wid; ++kt) {
        if (kt > 0) {
            // S chunk (kt >= 1); kt==0's sa already computed above
            const uint32_t kBase = uK + bOffK + (uint32_t)(kt * 16 * QPH) * 2;
            uint32_t kf[4][4];
#pragma unroll
            for (int kk = 0; kk < 4; ++kk)
                LDSM4(kf[kk][0], kf[kk][1], kf[kk][2], kf[kk][3], kBase + kk * 32);
            sa[0][0] = sa[0][1] = sa[0][2] = sa[0][3] = 0.f;
            sa[1][0] = sa[1][1] = sa[1][2] = sa[1][3] = 0.f;
#pragma unroll
            for (int kk = 0; kk < 4; ++kk) {
                uint32_t bf0[2] = {kf[kk][0], kf[kk][1]}, bf1[2] = {kf[kk][2], kf[kk][3]};
                mma_f16(sa[0], qf[kk], bf0);
                mma_f16(sa[1], qf[kk], bf1);
            }
        }

        const uint32_t vBase = uV + bOffV + (uint32_t)(kt * 16 * QPH) * 2;
        uint32_t vf[4][4];
#pragma unroll
        for (int j2 = 0; j2 < 4; ++j2)
            LDSM4T(vf[j2][0], vf[j2][1], vf[j2][2], vf[j2][3],
                   vBase + (uint32_t)(j2 * 16) * 2);

        // mask + exp + rowsum
        const bool diag = (kt == wid);
#pragma unroll
        for (int j = 0; j < 2; ++j)
#pragma unroll
            for (int e = 0; e < 4; ++e) {
                int col  = j * 8 + 2 * ctg + (e & 1);
                int rowi = gr + ((e >= 2) ? 8 : 0);
                float v = (!diag || (col <= rowi)) ?
                          __expf(sa[j][e] * 0.125f) : 0.f;
                sa[j][e] = v;
                if (e < 2) rs0 += v; else rs1 += v;
            }

        // P c-frag -> A-frag
        uint32_t pa[4];
        {
            __half2 t0 = __floats2half2_rn(sa[0][0], sa[0][1]);
            __half2 t1 = __floats2half2_rn(sa[0][2], sa[0][3]);
            __half2 t2 = __floats2half2_rn(sa[1][0], sa[1][1]);
            __half2 t3 = __floats2half2_rn(sa[1][2], sa[1][3]);
            pa[0] = *(uint32_t*)&t0;  pa[1] = *(uint32_t*)&t1;
            pa[2] = *(uint32_t*)&t2;  pa[3] = *(uint32_t*)&t3;
        }

        // P·V
#pragma unroll
        for (int j2 = 0; j2 < 4; ++j2) {
            uint32_t bf0[2] = {vf[j2][0], vf[j2][1]}, bf1[2] = {vf[j2][2], vf[j2][3]};
            mma_f16(oa[2 * j2],     pa, bf0);
            mma_f16(oa[2 * j2 + 1], pa, bf1);
        }
    }

    {
        float s0 = rs0, s1 = rs1;
        s0 += __shfl_xor_sync(0xffffffffu, s0, 1);
        s0 += __shfl_xor_sync(0xffffffffu, s0, 2);
        s1 += __shfl_xor_sync(0xffffffffu, s1, 1);
        s1 += __shfl_xor_sync(0xffffffffu, s1, 2);
        float inv0 = __fdividef(1.f, s0 + 1e-6f);
        float inv1 = __fdividef(1.f, s1 + 1e-6f);

        __half* op = outp + (size_t)token0 * C_ + h * Dh_;
        int r0 = wid * 16 + gr;
#pragma unroll
        for (int jt = 0; jt < 8; ++jt) {
            int c0 = jt * 8 + 2 * ctg;
            __half2 v0 = __floats2half2_rn(oa[jt][0] * inv0, oa[jt][1] * inv0);
            __half2 v1 = __floats2half2_rn(oa[jt][2] * inv1, oa[jt][3] * inv1);
            *(__half2*)&op[(size_t)r0 * C_ + c0]       = v0;
            *(__half2*)&op[(size_t)(r0 + 8) * C_ + c0] = v1;
        }
    }
}

// ---------------------------------------------------------------------------
extern "C" void kernel_launch(void* const* d_in, const int* in_sizes, int n_in,
                              void* d_out, int out_size)
{
    const float* x      = (const float*)d_in[0];
    const float* W_qkv  = (const float*)d_in[1];
    const float* W_proj = (const float*)d_in[2];
    const float* b_proj = (const float*)d_in[3];
    float* out = (float*)d_out;

    __half *qkvh, *attnh, *xh, *WqkvT, *WprojT;
    cudaGetSymbolAddress((void**)&qkvh,   g_qkvh);
    cudaGetSymbolAddress((void**)&attnh,  g_attnh);
    cudaGetSymbolAddress((void**)&xh,     g_xh);
    cudaGetSymbolAddress((void**)&WqkvT,  g_WqkvT);
    cudaGetSymbolAddress((void**)&WprojT, g_WprojT);

    static bool attr_set = false;
    if (!attr_set) {
        cudaFuncSetAttribute((const void*)gemm_h<false, true>,
                             cudaFuncAttributeMaxDynamicSharedMemorySize, GSMEM_B);
        cudaFuncSetAttribute((const void*)gemm_h<true, false>,
                             cudaFuncAttributeMaxDynamicSharedMemorySize, GSMEM_B);
        cudaFuncSetAttribute((const void*)attn_h,
                             cudaFuncAttributeMaxDynamicSharedMemorySize, ATT2_B);
        attr_set = true;
    }

    // 0) fp16 conversions
    cvt_f2h<<<(M_TOK * C_ / 4 + 255) / 256, 256>>>((const float4*)x, (uint2*)xh,
                                                   M_TOK * C_ / 4);
    transpose_cvt<<<dim3(N_QKV / 32, KDIM / 32), dim3(32, 8)>>>(W_qkv, WqkvT, KDIM, N_QKV);
    transpose_cvt<<<dim3(C_ / 32, KDIM / 32), dim3(32, 8)>>>(W_proj, WprojT, KDIM, C_);

    // 1) qkv = x @ W_qkv  (fp16 mma, fp16 out)
    gemm_h<false, true><<<dim3(N_QKV / 128, M_TOK / 128), 128, GSMEM_B>>>(
        xh, WqkvT, nullptr, qkvh, N_QKV);

    // 2) block-local causal attention (fp16 mma, async split loads)
    attn_h<<<dim3(H_, T_ / BS_, B_), 256, ATT2_B>>>(qkvh, attnh);

    // 3) out = attn @ W_proj + b_proj (fp16 mma, fp32 out)
    gemm_h<true, false><<<dim3(C_ / 128, M_TOK / 128), 128, GSMEM_B>>>(
        attnh, WprojT, b_proj, out, C_);
}

// round 17
// speedup vs baseline: 1.0383x; 1.0032x over previous
#include <cuda_runtime.h>
#include <cuda_fp16.h>
#include <cstdint>

// Problem constants (B=4, T=4096, C=1024, H=16, D=64, BLOCK=128)
#define B_    4
#define T_    4096
#define C_    1024
#define H_    16
#define Dh_   64
#define BS_   128
#define M_TOK 16384
#define N_QKV 3072
#define KDIM  1024

// Scratch (allocation-free rule: __device__ globals)
__device__ __half g_qkvh  [(size_t)M_TOK * N_QKV];  // 96 MiB
__device__ __half g_attnh [(size_t)M_TOK * C_];     // 32 MiB
__device__ __half g_xh    [(size_t)M_TOK * C_];     // 32 MiB
__device__ __half g_WqkvT [(size_t)N_QKV * KDIM];   // 6 MiB  [N][K]
__device__ __half g_WprojT[(size_t)C_ * KDIM];      // 2 MiB  [N][K]

// ---------------------------------------------------------------------------
// helpers
// ---------------------------------------------------------------------------
__device__ __forceinline__ uint32_t smem_u32(const void* p) {
    uint32_t a;
    asm("{ .reg .u64 t; cvta.to.shared.u64 t, %1; cvt.u32.u64 %0, t; }" : "=r"(a) : "l"(p));
    return a;
}
// D += A*B, m16n8k16 f16 inputs, f32 accum
__device__ __forceinline__ void mma_f16(float* d, const uint32_t* a, const uint32_t* b) {
    asm volatile(
        "mma.sync.aligned.m16n8k16.row.col.f32.f16.f16.f32 "
        "{%0,%1,%2,%3}, {%4,%5,%6,%7}, {%8,%9}, {%0,%1,%2,%3};"
        : "+f"(d[0]), "+f"(d[1]), "+f"(d[2]), "+f"(d[3])
        : "r"(a[0]), "r"(a[1]), "r"(a[2]), "r"(a[3]), "r"(b[0]), "r"(b[1]));
}
#define LDSM4(r0, r1, r2, r3, addr) \
    asm volatile("ldmatrix.sync.aligned.m8n8.x4.shared.b16 {%0,%1,%2,%3}, [%4];" \
                 : "=r"(r0), "=r"(r1), "=r"(r2), "=r"(r3) : "r"(addr))
#define LDSM4T(r0, r1, r2, r3, addr) \
    asm volatile("ldmatrix.sync.aligned.m8n8.x4.trans.shared.b16 {%0,%1,%2,%3}, [%4];" \
                 : "=r"(r0), "=r"(r1), "=r"(r2), "=r"(r3) : "r"(addr))
#define CP16(dst, src) \
    asm volatile("cp.async.cg.shared.global [%0], [%1], 16;" :: "r"(dst), "l"(src))
#define CP_COMMIT() asm volatile("cp.async.commit_group;")
#define CP_WAIT0()  asm volatile("cp.async.wait_group 0;")
#define CP_WAIT1()  asm volatile("cp.async.wait_group 1;")

// ---------------------------------------------------------------------------
// conversion kernels
// ---------------------------------------------------------------------------
__global__ void cvt_f2h(const float4* __restrict__ in, uint2* __restrict__ out, int n4) {
    int i = blockIdx.x * blockDim.x + threadIdx.x;
    if (i < n4) {
        float4 v = in[i];
        __half2 h0 = __floats2half2_rn(v.x, v.y);
        __half2 h1 = __floats2half2_rn(v.z, v.w);
        out[i] = make_uint2(*(uint32_t*)&h0, *(uint32_t*)&h1);
    }
}
// in fp32 [R][Cc] -> out half [Cc][R]
__global__ void transpose_cvt(const float* __restrict__ in, __half* __restrict__ out,
                              int R, int Cc)
{
    __shared__ float t[32][33];
    int x = blockIdx.x * 32 + threadIdx.x;
    int y = blockIdx.y * 32 + threadIdx.y;
#pragma unroll
    for (int j = 0; j < 32; j += 8)
        t[threadIdx.y + j][threadIdx.x] = in[(size_t)(y + j) * Cc + x];
    __syncthreads();
    int x2 = blockIdx.y * 32 + threadIdx.x;
    int y2 = blockIdx.x * 32 + threadIdx.y;
#pragma unroll
    for (int j = 0; j < 32; j += 8)
        out[(size_t)(y2 + j) * R + x2] = __float2half(t[threadIdx.x][threadIdx.y + j]);
}

// ---------------------------------------------------------------------------
// fp16 mma GEMM (verbatim R14 — best measured): 128x128 CTA tiles, BK=64,
// 3-stage cp.async, 4 warps (2x2), 64x64 warp tile, ldmatrix, XOR swizzle,
// fragment double buffering with cross-iteration prefetch.
// ---------------------------------------------------------------------------
#define ROWB     128
#define ASTG_B   (128 * ROWB)
#define STG_B    (2 * ASTG_B)
#define GSMEM_B  (3 * STG_B)

__device__ __forceinline__ uint32_t swz(uint32_t row, uint32_t g) {
    return row * ROWB + (((g ^ (row & 7)) & 7) << 4);
}

template <bool BIAS, bool HALF_OUT>
__global__ __launch_bounds__(128, 2)
void gemm_h(const __half* __restrict__ A, const __half* __restrict__ Bt,
            const float* __restrict__ bias, void* __restrict__ Cout, int N)
{
    extern __shared__ __half smh[];
    const uint32_t sb = smem_u32(smh);
    const int tid = threadIdx.x, lane = tid & 31, wid = tid >> 5;
    const int wm = wid >> 1, wn = wid & 1, gr = lane >> 2, ctg = lane & 3;
    const int bm = blockIdx.y * 128, bn = blockIdx.x * 128;

    const __half* pA = A + (size_t)(bm + (tid >> 3)) * KDIM + (tid & 7) * 8;
    const __half* pB = Bt + (size_t)(bn + (tid >> 3)) * KDIM + (tid & 7) * 8;
    const uint32_t dA0 = sb + swz((uint32_t)(tid >> 3), (uint32_t)(tid & 7));
    const uint32_t dB0 = dA0 + ASTG_B;

    auto load_tile = [&](int s, int k0) {
        const uint32_t so = (uint32_t)(s * STG_B);
#pragma unroll
        for (int i = 0; i < 8; i++)
            CP16(dA0 + so + (uint32_t)(i * 16 * ROWB), pA + k0 + (size_t)i * 16 * KDIM);
#pragma unroll
        for (int i = 0; i < 8; i++)
            CP16(dB0 + so + (uint32_t)(i * 16 * ROWB), pB + k0 + (size_t)i * 16 * KDIM);
    };

    const uint32_t rA  = (uint32_t)(wm * 64 + (lane & 15));
    const uint32_t gA0 = (uint32_t)(lane >> 4);
    const uint32_t rB  = (uint32_t)(wn * 64 + ((lane & 16) >> 1) + (lane & 7));
    const uint32_t gB0 = (uint32_t)((lane & 8) >> 3);

    float acc[4][8][4] = {};
    uint32_t a[2][4][4], bf[2][8][2];

    auto ldfrags = [&](int buf, uint32_t sA, uint32_t sB, int kk) {
        const uint32_t gA = 2 * kk + gA0;
        const uint32_t gB = 2 * kk + gB0;
#pragma unroll
        for (int mi = 0; mi < 4; ++mi)
            LDSM4(a[buf][mi][0], a[buf][mi][1], a[buf][mi][2], a[buf][mi][3],
                  sA + swz(rA + mi * 16, gA));
#pragma unroll
        for (int pn = 0; pn < 4; ++pn)
            LDSM4(bf[buf][2 * pn][0], bf[buf][2 * pn][1],
                  bf[buf][2 * pn + 1][0], bf[buf][2 * pn + 1][1],
                  sB + swz(rB + pn * 16, gB));
    };

    // prologue: tiles 0 and 1 both complete & visible, frags for (tile0,kk0)
    load_tile(0, 0);  CP_COMMIT();
    load_tile(1, 64); CP_COMMIT();
    CP_WAIT0();
    __syncthreads();
    ldfrags(0, sb, sb + ASTG_B, 0);

    for (int it = 0; it < 16; ++it) {
        const uint32_t sA = sb + (uint32_t)((it % 3) * STG_B);
        const uint32_t sB = sA + ASTG_B;
        const uint32_t nA = sb + (uint32_t)(((it + 1) % 3) * STG_B);
        const uint32_t nB = nA + ASTG_B;

        if (it + 2 < 16) { load_tile((it + 2) % 3, (it + 2) * 64); CP_COMMIT(); }

#pragma unroll
        for (int kk = 0; kk < 4; ++kk) {
            const int cur = kk & 1;
            if (kk < 3)       ldfrags(cur ^ 1, sA, sB, kk + 1);
            else if (it < 15) ldfrags(cur ^ 1, nA, nB, 0);   // cross-iter prefetch
#pragma unroll
            for (int mi = 0; mi < 4; ++mi)
#pragma unroll
                for (int ni = 0; ni < 8; ++ni)
                    mma_f16(acc[mi][ni], a[cur][mi], bf[cur][ni]);
        }

        if (it + 2 < 16) {
            CP_WAIT0();
            __syncthreads();
        }
    }

#pragma unroll
    for (int mi = 0; mi < 4; mi++) {
        int r0 = bm + wm * 64 + mi * 16 + gr;
#pragma unroll
        for (int ni = 0; ni < 8; ni++) {
            int c0 = bn + wn * 64 + ni * 8 + 2 * ctg;
            if (HALF_OUT) {
                __half* C = (__half*)Cout;
                __half2 v0 = __floats2half2_rn(acc[mi][ni][0], acc[mi][ni][1]);
                __half2 v1 = __floats2half2_rn(acc[mi][ni][2], acc[mi][ni][3]);
                *(__half2*)&C[(size_t)r0 * N + c0]       = v0;
                *(__half2*)&C[(size_t)(r0 + 8) * N + c0] = v1;
            } else {
                float* C = (float*)Cout;
                float bx = 0.f, by = 0.f;
                if (BIAS) { bx = bias[c0]; by = bias[c0 + 1]; }
                float2 v0 = make_float2(acc[mi][ni][0] + bx, acc[mi][ni][1] + by);
                float2 v1 = make_float2(acc[mi][ni][2] + bx, acc[mi][ni][3] + by);
                *(float2*)&C[(size_t)r0 * N + c0]       = v0;
                *(float2*)&C[(size_t)(r0 + 8) * N + c0] = v1;
            }
        }
    }
}

// ---------------------------------------------------------------------------
// Block-local causal attention — R16 async front-end, inline fragment loads,
// register diet + __launch_bounds__(256, 3) to reach 3 CTAs/SM (24 warps).
// grid = (H, T/128, B), 256 threads; Q frags hoisted.
// ---------------------------------------------------------------------------
#define QPH 72
#define AOFF_Q 0
#define AOFF_K (128 * QPH)
#define AOFF_V (2 * 128 * QPH)
#define ATT2_B (3 * 128 * QPH * 2)           // 55296 bytes

__global__ __launch_bounds__(256, 3)
void attn_h(const __half* __restrict__ qkv, __half* __restrict__ outp)
{
    extern __shared__ __half smh[];
    const uint32_t sbA = smem_u32(smh);
    const int h = blockIdx.x, blk = blockIdx.y, b = blockIdx.z;
    const int token0 = b * T_ + blk * BS_;
    const __half* qp = qkv + (size_t)token0 * N_QKV + h * Dh_;
    const __half* kp = qp + C_;
    const __half* vp = qp + 2 * C_;

    const int tid = threadIdx.x, lane = tid & 31, wid = tid >> 5;
    const int gr = lane >> 2, ctg = lane & 3;

    const uint32_t uQ = sbA + AOFF_Q * 2;
    const uint32_t uK = sbA + AOFF_K * 2;
    const uint32_t uV = sbA + AOFF_V * 2;

    // async fill: group 0 = Q+K, group 1 = V (each thread: 4 rows x 16B)
    {
        const int r = tid >> 3, c8 = (tid & 7) << 3;
        const uint32_t so = (uint32_t)(r * QPH + c8) * 2;
        const size_t go = (size_t)r * N_QKV + c8;
#pragma unroll
        for (int i = 0; i < 4; ++i) {
            CP16(uQ + so + (uint32_t)(i * 32 * QPH) * 2, qp + go + (size_t)i * 32 * N_QKV);
            CP16(uK + so + (uint32_t)(i * 32 * QPH) * 2, kp + go + (size_t)i * 32 * N_QKV);
        }
        CP_COMMIT();
#pragma unroll
        for (int i = 0; i < 4; ++i)
            CP16(uV + so + (uint32_t)(i * 32 * QPH) * 2, vp + go + (size_t)i * 32 * N_QKV);
        CP_COMMIT();
    }

    const uint32_t aOffQ = (uint32_t)((wid * 16 + (lane & 15)) * QPH + ((lane >> 4) << 3)) * 2;
    const uint32_t bOffK = (uint32_t)((((lane & 16) >> 1) + (lane & 7)) * QPH
                                      + ((lane & 8) ? 8 : 0)) * 2;
    const uint32_t bOffV = (uint32_t)(((lane & 7) + ((lane & 8) ? 8 : 0)) * QPH
                                      + ((lane & 16) ? 8 : 0)) * 2;

    CP_WAIT1();            // Q, K visible (after barrier)
    __syncthreads();

    // hoist Q fragments (invariant across kt)
    uint32_t qf[4][4];
#pragma unroll
    for (int kk = 0; kk < 4; ++kk)
        LDSM4(qf[kk][0], qf[kk][1], qf[kk][2], qf[kk][3], uQ + aOffQ + kk * 32);

    float oa[8][4] = {};
    float rs0 = 0.f, rs1 = 0.f;

    // ---- peeled chunk kt = 0: S while V is still loading (inline K loads) ----
    float sa[2][4] = {};
#pragma unroll
    for (int kk = 0; kk < 4; ++kk) {
        uint32_t b0, b1, b2, b3;
        LDSM4(b0, b1, b2, b3, uK + bOffK + kk * 32);
        uint32_t bf0[2] = {b0, b1}, bf1[2] = {b2, b3};
        mma_f16(sa[0], qf[kk], bf0);
        mma_f16(sa[1], qf[kk], bf1);
    }

    CP_WAIT0();            // V visible (after barrier)
    __syncthreads();

    for (int kt = 0; kt <= wid; ++kt) {
        if (kt > 0) {
            const uint32_t kBase = uK + bOffK + (uint32_t)(kt * 16 * QPH) * 2;
            sa[0][0] = sa[0][1] = sa[0][2] = sa[0][3] = 0.f;
            sa[1][0] = sa[1][1] = sa[1][2] = sa[1][3] = 0.f;
#pragma unroll
            for (int kk = 0; kk < 4; ++kk) {
                uint32_t b0, b1, b2, b3;
                LDSM4(b0, b1, b2, b3, kBase + kk * 32);
                uint32_t bf0[2] = {b0, b1}, bf1[2] = {b2, b3};
                mma_f16(sa[0], qf[kk], bf0);
                mma_f16(sa[1], qf[kk], bf1);
            }
        }

        // mask + exp + rowsum
        const bool diag = (kt == wid);
#pragma unroll
        for (int j = 0; j < 2; ++j)
#pragma unroll
            for (int e = 0; e < 4; ++e) {
                int col  = j * 8 + 2 * ctg + (e & 1);
                int rowi = gr + ((e >= 2) ? 8 : 0);
                float v = (!diag || (col <= rowi)) ?
                          __expf(sa[j][e] * 0.125f) : 0.f;
                sa[j][e] = v;
                if (e < 2) rs0 += v; else rs1 += v;
            }

        // P c-frag -> A-frag
        uint32_t pa[4];
        {
            __half2 t0 = __floats2half2_rn(sa[0][0], sa[0][1]);
            __half2 t1 = __floats2half2_rn(sa[0][2], sa[0][3]);
            __half2 t2 = __floats2half2_rn(sa[1][0], sa[1][1]);
            __half2 t3 = __floats2half2_rn(sa[1][2], sa[1][3]);
            pa[0] = *(uint32_t*)&t0;  pa[1] = *(uint32_t*)&t1;
            pa[2] = *(uint32_t*)&t2;  pa[3] = *(uint32_t*)&t3;
        }

        // P·V (inline V loads)
        const uint32_t vBase = uV + bOffV + (uint32_t)(kt * 16 * QPH) * 2;
#pragma unroll
        for (int j2 = 0; j2 < 4; ++j2) {
            uint32_t v0, v1, v2, v3;
            LDSM4T(v0, v1, v2, v3, vBase + (uint32_t)(j2 * 16) * 2);
            uint32_t bf0[2] = {v0, v1}, bf1[2] = {v2, v3};
            mma_f16(oa[2 * j2],     pa, bf0);
            mma_f16(oa[2 * j2 + 1], pa, bf1);
        }
    }

    {
        float s0 = rs0, s1 = rs1;
        s0 += __shfl_xor_sync(0xffffffffu, s0, 1);
        s0 += __shfl_xor_sync(0xffffffffu, s0, 2);
        s1 += __shfl_xor_sync(0xffffffffu, s1, 1);
        s1 += __shfl_xor_sync(0xffffffffu, s1, 2);
        float inv0 = __fdividef(1.f, s0 + 1e-6f);
        float inv1 = __fdividef(1.f, s1 + 1e-6f);

        __half* op = outp + (size_t)token0 * C_ + h * Dh_;
        int r0 = wid * 16 + gr;
#pragma unroll
        for (int jt = 0; jt < 8; ++jt) {
            int c0 = jt * 8 + 2 * ctg;
            __half2 v0 = __floats2half2_rn(oa[jt][0] * inv0, oa[jt][1] * inv0);
            __half2 v1 = __floats2half2_rn(oa[jt][2] * inv1, oa[jt][3] * inv1);
            *(__half2*)&op[(size_t)r0 * C_ + c0]       = v0;
            *(__half2*)&op[(size_t)(r0 + 8) * C_ + c0] = v1;
        }
    }
}

// ---------------------------------------------------------------------------
extern "C" void kernel_launch(void* const* d_in, const int* in_sizes, int n_in,
                              void* d_out, int out_size)
{
    const float* x      = (const float*)d_in[0];
    const float* W_qkv  = (const float*)d_in[1];
    const float* W_proj = (const float*)d_in[2];
    const float* b_proj = (const float*)d_in[3];
    float* out = (float*)d_out;

    __half *qkvh, *attnh, *xh, *WqkvT, *WprojT;
    cudaGetSymbolAddress((void**)&qkvh,   g_qkvh);
    cudaGetSymbolAddress((void**)&attnh,  g_attnh);
    cudaGetSymbolAddress((void**)&xh,     g_xh);
    cudaGetSymbolAddress((void**)&WqkvT,  g_WqkvT);
    cudaGetSymbolAddress((void**)&WprojT, g_WprojT);

    static bool attr_set = false;
    if (!attr_set) {
        cudaFuncSetAttribute((const void*)gemm_h<false, true>,
                             cudaFuncAttributeMaxDynamicSharedMemorySize, GSMEM_B);
        cudaFuncSetAttribute((const void*)gemm_h<true, false>,
                             cudaFuncAttributeMaxDynamicSharedMemorySize, GSMEM_B);
        cudaFuncSetAttribute((const void*)attn_h,
                             cudaFuncAttributeMaxDynamicSharedMemorySize, ATT2_B);
        attr_set = true;
    }

    // 0) fp16 conversions
    cvt_f2h<<<(M_TOK * C_ / 4 + 255) / 256, 256>>>((const float4*)x, (uint2*)xh,
                                                   M_TOK * C_ / 4);
    transpose_cvt<<<dim3(N_QKV / 32, KDIM / 32), dim3(32, 8)>>>(W_qkv, WqkvT, KDIM, N_QKV);
    transpose_cvt<<<dim3(C_ / 32, KDIM / 32), dim3(32, 8)>>>(W_proj, WprojT, KDIM, C_);

    // 1) qkv = x @ W_qkv  (fp16 mma, fp16 out)
    gemm_h<false, true><<<dim3(N_QKV / 128, M_TOK / 128), 128, GSMEM_B>>>(
        xh, WqkvT, nullptr, qkvh, N_QKV);

    // 2) block-local causal attention (fp16 mma, async loads, 3 CTAs/SM)
    attn_h<<<dim3(H_, T_ / BS_, B_), 256, ATT2_B>>>(qkvh, attnh);

    // 3) out = attn @ W_proj + b_proj (fp16 mma, fp32 out)
    gemm_h<true, false><<<dim3(C_ / 128, M_TOK / 128), 128, GSMEM_B>>>(
        attnh, WprojT, b_proj, out, C_);
}